// round 1
// baseline (speedup 1.0000x reference)
#include <cuda_runtime.h>
#include <cuda_bf16.h>
#include <stdint.h>

// Problem constants (fixed by the dataset)
#define B_Q   4096
#define P_POS 4
#define DIM   768
#define N_KEY (B_Q + B_Q * P_POS)   // 20480
#define NBN   (N_KEY / 128)         // 160 column tiles
#define NBM   (B_Q / 128)           // 32 row tiles

// TEMPERATURE = 0.07
#define INV_T        14.285714285714286f
#define LOG2E_OVER_T 20.609929155556620f

// ---------------- scratch (allocation-free contract: __device__ globals) ----
__device__ __nv_bfloat16 g_keys[(size_t)N_KEY * DIM];   // normalized q rows then doc rows
__device__ float g_part[(size_t)B_Q * NBN];             // per (row, col-tile) partial exp-sums
__device__ float g_S[B_Q];                              // full row sums
__device__ float g_sa[B_Q * P_POS];                     // positive dots (fp32, from bf16 keys)
__device__ float g_diag[B_Q];                           // self dots (fp32, from bf16 keys)

// ---------------- fast exp(dot / T) = 2^(dot * log2e/T), FFMA-only ----------
// |dot| <= ~1  ->  |y| <= ~21.  Avoids MUFU (EX2 rt would bottleneck at ~600us).
__device__ __forceinline__ float fexp_t(float dot) {
    float y  = dot * LOG2E_OVER_T;
    float z  = y + 12582912.0f;              // 1.5 * 2^23 : forces round-to-nearest int
    int   iz = __float_as_int(z);            // low mantissa bits hold rint(y) (+0x400000)
    float fi = z - 12582912.0f;              // rint(y) as float
    float f  = y - fi;                       // f in [-0.5, 0.5], exact
    float p  = 1.3333558146e-3f;             // 2^f, Taylor deg-5 (rel err ~2e-6)
    p = fmaf(p, f, 9.6181291076e-3f);
    p = fmaf(p, f, 5.5504108665e-2f);
    p = fmaf(p, f, 2.4022650696e-1f);
    p = fmaf(p, f, 6.9314718056e-1f);
    p = fmaf(p, f, 1.0f);
    float s = __int_as_float((iz << 23) + 0x3f800000);   // 2^rint(y)
    return p * s;
}

// ---------------- kernel 1: L2-normalize rows, write bf16 keys --------------
__global__ void prep_normalize(const float* __restrict__ q,
                               const float* __restrict__ docs) {
    int row = blockIdx.x;
    int t   = threadIdx.x;
    const float* src = (row < B_Q) ? (q + (size_t)row * DIM)
                                   : (docs + (size_t)(row - B_Q) * DIM);
    float ss = 0.f;
    for (int j = t; j < DIM; j += 256) { float v = src[j]; ss = fmaf(v, v, ss); }
    __shared__ float red[256];
    red[t] = ss; __syncthreads();
    for (int s = 128; s > 0; s >>= 1) { if (t < s) red[t] += red[t + s]; __syncthreads(); }
    float nrm = sqrtf(red[0]);
    float sc  = 1.0f / fmaxf(nrm, 1e-12f);
    __nv_bfloat16* dst = g_keys + (size_t)row * DIM;
    for (int j = t; j < DIM; j += 256) dst[j] = __float2bfloat16(src[j] * sc);
}

// ---------------- kernel 2: positive dots + self dot (fp32, bf16 inputs) ----
// 5 warps: warps 0..3 -> positives, warp 4 -> self dot (for exact diag cancel)
__global__ void pos_diag_dots() {
    int i = blockIdx.x;
    int w = threadIdx.x >> 5, l = threadIdx.x & 31;
    const __nv_bfloat16* qa = g_keys + (size_t)i * DIM;
    const __nv_bfloat16* kb = (w < 4) ? (g_keys + (size_t)(B_Q + i * P_POS + w) * DIM) : qa;
    float s = 0.f;
    for (int j = l; j < DIM; j += 32)
        s = fmaf(__bfloat162float(qa[j]), __bfloat162float(kb[j]), s);
    for (int o = 16; o > 0; o >>= 1) s += __shfl_xor_sync(0xffffffffu, s, o);
    if (l == 0) { if (w < 4) g_sa[i * P_POS + w] = s; else g_diag[i] = s; }
}

// ---------------- mma.sync m16n8k16 bf16 ------------------------------------
__device__ __forceinline__ void mma16816(float* c, const uint32_t* a, const uint32_t* b) {
    asm volatile(
        "mma.sync.aligned.m16n8k16.row.col.f32.bf16.bf16.f32 "
        "{%0,%1,%2,%3}, {%4,%5,%6,%7}, {%8,%9}, {%0,%1,%2,%3};"
        : "+f"(c[0]), "+f"(c[1]), "+f"(c[2]), "+f"(c[3])
        : "r"(a[0]), "r"(a[1]), "r"(a[2]), "r"(a[3]), "r"(b[0]), "r"(b[1]));
}

// ---------------- kernel 3: GEMM q @ keys^T, fused exp + row-sum ------------
// BM=BN=128, BK=32, 8 warps (4M x 2N), warp tile 32x64. Deterministic output:
// per-CTA partials to g_part (no atomics).
__global__ __launch_bounds__(256, 2) void gemm_exp_rowsum() {
    __shared__ __align__(16) __nv_bfloat16 As[128][40];  // pad 8 -> conflict-free
    __shared__ __align__(16) __nv_bfloat16 Bs[128][40];
    __shared__ float rsum[2][128];

    int t    = threadIdx.x;
    int bn   = blockIdx.x;           // 0..159
    int bm   = blockIdx.y;           // 0..31
    int warp = t >> 5, lane = t & 31;
    int wm   = warp >> 1, wn = warp & 1;
    int lr   = lane >> 2, lc = (lane & 3) * 2;

    float c[2][8][4];
    #pragma unroll
    for (int mt = 0; mt < 2; ++mt)
        #pragma unroll
        for (int nt = 0; nt < 8; ++nt)
            #pragma unroll
            for (int r = 0; r < 4; ++r) c[mt][nt][r] = 0.f;

    const __nv_bfloat16* Aptr = g_keys + (size_t)bm * 128 * DIM;
    const __nv_bfloat16* Bptr = g_keys + (size_t)bn * 128 * DIM;

    for (int kt = 0; kt < DIM / 32; ++kt) {
        int k0 = kt * 32;
        __syncthreads();
        #pragma unroll
        for (int h = 0; h < 2; ++h) {
            int ch = t + h * 256;            // 512 chunks of 16B per operand
            int r  = ch >> 2;
            int kc = (ch & 3) * 8;
            *(uint4*)&As[r][kc] = *(const uint4*)&Aptr[(size_t)r * DIM + k0 + kc];
            *(uint4*)&Bs[r][kc] = *(const uint4*)&Bptr[(size_t)r * DIM + k0 + kc];
        }
        __syncthreads();
        #pragma unroll
        for (int ks = 0; ks < 2; ++ks) {
            int kb = ks * 16;
            uint32_t a[2][4], b[8][2];
            #pragma unroll
            for (int mt = 0; mt < 2; ++mt) {
                int r = wm * 32 + mt * 16 + lr;
                a[mt][0] = *(const uint32_t*)&As[r    ][kb + lc];
                a[mt][1] = *(const uint32_t*)&As[r + 8][kb + lc];
                a[mt][2] = *(const uint32_t*)&As[r    ][kb + 8 + lc];
                a[mt][3] = *(const uint32_t*)&As[r + 8][kb + 8 + lc];
            }
            #pragma unroll
            for (int nt = 0; nt < 8; ++nt) {
                int rn = wn * 64 + nt * 8 + lr;
                b[nt][0] = *(const uint32_t*)&Bs[rn][kb + lc];
                b[nt][1] = *(const uint32_t*)&Bs[rn][kb + 8 + lc];
            }
            #pragma unroll
            for (int mt = 0; mt < 2; ++mt)
                #pragma unroll
                for (int nt = 0; nt < 8; ++nt)
                    mma16816(c[mt][nt], a[mt], b[nt]);
        }
    }

    // epilogue: exp each accum (FFMA poly), reduce 64 cols per warp, rows unique
    #pragma unroll
    for (int mt = 0; mt < 2; ++mt) {
        float s0 = 0.f, s1 = 0.f;
        #pragma unroll
        for (int nt = 0; nt < 8; ++nt) {
            s0 += fexp_t(c[mt][nt][0]) + fexp_t(c[mt][nt][1]);
            s1 += fexp_t(c[mt][nt][2]) + fexp_t(c[mt][nt][3]);
        }
        s0 += __shfl_xor_sync(0xffffffffu, s0, 1);
        s0 += __shfl_xor_sync(0xffffffffu, s0, 2);
        s1 += __shfl_xor_sync(0xffffffffu, s1, 1);
        s1 += __shfl_xor_sync(0xffffffffu, s1, 2);
        if ((lane & 3) == 0) {
            rsum[wn][wm * 32 + mt * 16 + lr]     = s0;
            rsum[wn][wm * 32 + mt * 16 + 8 + lr] = s1;
        }
    }
    __syncthreads();
    if (t < 128)
        g_part[(size_t)(bm * 128 + t) * NBN + bn] = rsum[0][t] + rsum[1][t];
}

// ---------------- kernel 4: reduce partials -> S[row] -----------------------
__global__ void reduce_S() {
    int row = blockIdx.x * 8 + (threadIdx.x >> 5);
    int l   = threadIdx.x & 31;
    float s = 0.f;
    for (int j = l; j < NBN; j += 32) s += g_part[(size_t)row * NBN + j];
    for (int o = 16; o > 0; o >>= 1) s += __shfl_xor_sync(0xffffffffu, s, o);
    if (l == 0) g_S[row] = s;
}

// ---------------- kernel 5: finalize loss ------------------------------------
__global__ void finalize_loss(float* __restrict__ out, int out_size) {
    int t = threadIdx.x;
    float acc = 0.f;
    for (int i = t; i < B_Q; i += 512) {
        float e[4], su = 0.f, sa[4];
        #pragma unroll
        for (int n = 0; n < 4; ++n) {
            sa[n] = g_sa[i * P_POS + n];
            e[n]  = fexp_t(sa[n]);
            su   += e[n];
        }
        float base = g_S[i] - fexp_t(g_diag[i]) - su;  // sim_q + sim_v - sim_u
        #pragma unroll
        for (int n = 0; n < 4; ++n)
            acc += logf(base + e[n]) - sa[n] * INV_T;  // -log(sim_a/denom)
    }
    __shared__ float red[512];
    red[t] = acc; __syncthreads();
    for (int s = 256; s > 0; s >>= 1) { if (t < s) red[t] += red[t + s]; __syncthreads(); }
    if (t == 0) {
        float loss = red[0] / (float)(B_Q * P_POS);
        for (int j = 0; j < out_size; ++j) out[j] = loss;
    }
}

// ---------------- launch ------------------------------------------------------
extern "C" void kernel_launch(void* const* d_in, const int* in_sizes, int n_in,
                              void* d_out, int out_size) {
    (void)in_sizes; (void)n_in;
    const float* q    = (const float*)d_in[0];
    const float* docs = (const float*)d_in[1];
    float* out        = (float*)d_out;

    prep_normalize<<<N_KEY, 256>>>(q, docs);
    pos_diag_dots<<<B_Q, 160>>>();
    gemm_exp_rowsum<<<dim3(NBN, NBM), 256>>>();
    reduce_S<<<B_Q / 8, 256>>>();
    finalize_loss<<<1, 512>>>(out, out_size);
}

// round 3
// speedup vs baseline: 1.5005x; 1.5005x over previous
#include <cuda_runtime.h>
#include <cuda_bf16.h>
#include <stdint.h>

// -------------------- problem constants --------------------
#define B_Q   4096
#define P_POS 4
#define DIM   768
#define N_KEY 20480               // B_Q + B_Q*P_POS

#define BM    128
#define BN    128
#define BK    64                  // 128 bytes per row per stage
#define KTILES (DIM / BK)         // 12
#define STAGES 3
#define NT_M  (B_Q / BM)          // 32
#define NT_N  (N_KEY / BN)        // 160

// TEMPERATURE = 0.07
#define INV_T        14.285714285714286f
#define LOG2E_OVER_T 20.609929155556620f

// -------------------- scratch (__device__ globals; no allocs) ----------------
__device__ __align__(256) __nv_bfloat16 g_keys[(size_t)N_KEY * DIM];
__device__ float g_part[(size_t)B_Q * NT_N];
__device__ float g_S[B_Q];
__device__ float g_sa[B_Q * P_POS];
__device__ float g_diag[B_Q];

// -------------------- PTX helpers --------------------
__device__ __forceinline__ uint32_t smem_u32(const void* p) {
    uint32_t a;
    asm("{ .reg .u64 t; cvta.to.shared.u64 t, %1; cvt.u32.u64 %0, t; }" : "=r"(a) : "l"(p));
    return a;
}
__device__ __forceinline__ float ex2f(float y) {
    float r; asm("ex2.approx.ftz.f32 %0, %1;" : "=f"(r) : "f"(y)); return r;
}
__device__ __forceinline__ void cp_async16(uint32_t dst, const void* src) {
    asm volatile("cp.async.cg.shared.global [%0], [%1], 16;" :: "r"(dst), "l"(src) : "memory");
}
__device__ __forceinline__ void cp_commit() {
    asm volatile("cp.async.commit_group;" ::: "memory");
}
template <int N>
__device__ __forceinline__ void cp_wait() {
    asm volatile("cp.async.wait_group %0;" :: "n"(N) : "memory");
}
__device__ __forceinline__ void ldsm_x4(uint32_t* r, uint32_t addr) {
    asm volatile("ldmatrix.sync.aligned.m8n8.x4.shared.b16 {%0,%1,%2,%3}, [%4];"
                 : "=r"(r[0]), "=r"(r[1]), "=r"(r[2]), "=r"(r[3]) : "r"(addr));
}
__device__ __forceinline__ void mma16816(float* c, const uint32_t* a, const uint32_t* b) {
    asm volatile(
        "mma.sync.aligned.m16n8k16.row.col.f32.bf16.bf16.f32 "
        "{%0,%1,%2,%3}, {%4,%5,%6,%7}, {%8,%9}, {%0,%1,%2,%3};"
        : "+f"(c[0]), "+f"(c[1]), "+f"(c[2]), "+f"(c[3])
        : "r"(a[0]), "r"(a[1]), "r"(a[2]), "r"(a[3]), "r"(b[0]), "r"(b[1]));
}

// -------------------- kernel 1: L2-normalize rows -> bf16 keys ---------------
__global__ void prep_normalize(const float* __restrict__ q,
                               const float* __restrict__ docs) {
    int row = blockIdx.x;
    int t   = threadIdx.x;
    const float* src = (row < B_Q) ? (q + (size_t)row * DIM)
                                   : (docs + (size_t)(row - B_Q) * DIM);
    float ss = 0.f;
    for (int j = t; j < DIM; j += 256) { float v = src[j]; ss = fmaf(v, v, ss); }
    __shared__ float red[256];
    red[t] = ss; __syncthreads();
    for (int s = 128; s > 0; s >>= 1) { if (t < s) red[t] += red[t + s]; __syncthreads(); }
    float sc = 1.0f / fmaxf(sqrtf(red[0]), 1e-12f);
    __nv_bfloat16* dst = g_keys + (size_t)row * DIM;
    for (int j = t; j < DIM; j += 256) dst[j] = __float2bfloat16(src[j] * sc);
}

// -------------------- kernel 2: positive + self dots (bf16-consistent) -------
__global__ void pos_diag_dots() {
    int i = blockIdx.x;
    int w = threadIdx.x >> 5, l = threadIdx.x & 31;
    const __nv_bfloat16* qa = g_keys + (size_t)i * DIM;
    const __nv_bfloat16* kb = (w < 4) ? (g_keys + (size_t)(B_Q + i * P_POS + w) * DIM) : qa;
    float s = 0.f;
    for (int j = l; j < DIM; j += 32)
        s = fmaf(__bfloat162float(qa[j]), __bfloat162float(kb[j]), s);
    for (int o = 16; o > 0; o >>= 1) s += __shfl_xor_sync(0xffffffffu, s, o);
    if (l == 0) { if (w < 4) g_sa[i * P_POS + w] = s; else g_diag[i] = s; }
}

// -------------------- kernel 3: pipelined mma.sync GEMM + fused exp/rowsum ---
// Dynamic SMEM: STAGES * (A 16KB + B 16KB). 128B rows, XOR-16B swizzle.
#define ST_A(s) ((s) * 32768)
#define ST_B(s) ((s) * 32768 + 16384)
#define SM_DYN  (STAGES * 32768)

__global__ __launch_bounds__(256, 2) void gemm_exp_rowsum() {
    extern __shared__ char smem[];
    __shared__ float rsum[4][128];
    uint32_t sb = smem_u32(smem);

    int t = threadIdx.x, warp = t >> 5, lane = t & 31;
    int bn = blockIdx.x, bm = blockIdx.y;
    int wm = warp >> 2, wn = warp & 3;          // 2 x 4 warps; warp tile 64(M) x 32(N)
    int gr = lane >> 2, gc = lane & 3;

    const char* Abase = (const char*)g_keys + (size_t)bm * BM * DIM * 2;
    const char* Bbase = (const char*)g_keys + (size_t)bn * BN * DIM * 2;

    // per-thread load slots: 4 chunks A + 4 chunks B (1024 chunks / 256 thr)
    int ar[4], ac[4];
    #pragma unroll
    for (int i = 0; i < 4; ++i) {
        int ch = i * 256 + t;
        ar[i] = ch >> 3; ac[i] = ch & 7;
    }

    #define ISSUE_STAGE(s, kt)                                                        \
        do {                                                                          \
            _Pragma("unroll")                                                         \
            for (int i = 0; i < 4; ++i) {                                             \
                uint32_t off = (uint32_t)(ar[i] * 128) +                              \
                               (uint32_t)((ac[i] * 16) ^ ((ar[i] & 7) << 4));         \
                cp_async16(sb + ST_A(s) + off,                                        \
                           Abase + (size_t)ar[i] * (DIM * 2) + (kt) * 128 + ac[i] * 16); \
                cp_async16(sb + ST_B(s) + off,                                        \
                           Bbase + (size_t)ar[i] * (DIM * 2) + (kt) * 128 + ac[i] * 16); \
            }                                                                         \
            cp_commit();                                                              \
        } while (0)

    ISSUE_STAGE(0, 0);
    ISSUE_STAGE(1, 1);

    float c[4][4][4];
    #pragma unroll
    for (int mt = 0; mt < 4; ++mt)
        #pragma unroll
        for (int nt = 0; nt < 4; ++nt)
            #pragma unroll
            for (int r = 0; r < 4; ++r) c[mt][nt][r] = 0.f;

    // ldmatrix lane-address components (row, 16B col within row)
    int a_mr = (lane & 15);                    // + wm*64 + mt*16
    int a_cb = (lane >> 4) * 16;               // + ks*32
    int b_nr = ((lane >> 3) & 1) * 8 + (lane & 7);   // + wn*32 + nt2*16
    int b_cb = (lane >> 4) * 16;               // + ks*32

    for (int kt = 0; kt < KTILES; ++kt) {
        int s = kt % STAGES;
        cp_wait<STAGES - 2>();
        __syncthreads();
        if (kt + STAGES - 1 < KTILES) ISSUE_STAGE((kt + STAGES - 1) % STAGES, kt + STAGES - 1);
        else cp_commit();

        uint32_t As = sb + ST_A(s), Bs = sb + ST_B(s);
        #pragma unroll
        for (int ks = 0; ks < 4; ++ks) {       // four k16 steps in BK=64
            uint32_t a[4][4], b[4][2];
            #pragma unroll
            for (int mt = 0; mt < 4; ++mt) {
                int mr = wm * 64 + mt * 16 + a_mr;
                uint32_t cb = (uint32_t)((ks * 32 + a_cb) ^ ((mr & 7) << 4));
                ldsm_x4(a[mt], As + mr * 128 + cb);
            }
            #pragma unroll
            for (int nt2 = 0; nt2 < 2; ++nt2) {
                int nr = wn * 32 + nt2 * 16 + b_nr;
                uint32_t cb = (uint32_t)((ks * 32 + b_cb) ^ ((nr & 7) << 4));
                uint32_t r4[4];
                ldsm_x4(r4, Bs + nr * 128 + cb);
                b[nt2 * 2 + 0][0] = r4[0]; b[nt2 * 2 + 0][1] = r4[2];
                b[nt2 * 2 + 1][0] = r4[1]; b[nt2 * 2 + 1][1] = r4[3];
            }
            #pragma unroll
            for (int mt = 0; mt < 4; ++mt)
                #pragma unroll
                for (int nt = 0; nt < 4; ++nt)
                    mma16816(c[mt][nt], a[mt], b[nt]);
        }
    }

    // ---- epilogue: exp + row-sum (nothing materialized) ----
    #pragma unroll
    for (int mt = 0; mt < 4; ++mt) {
        float s0 = 0.f, s1 = 0.f;
        #pragma unroll
        for (int nt = 0; nt < 4; ++nt) {
            s0 += ex2f(c[mt][nt][0] * LOG2E_OVER_T) + ex2f(c[mt][nt][1] * LOG2E_OVER_T);
            s1 += ex2f(c[mt][nt][2] * LOG2E_OVER_T) + ex2f(c[mt][nt][3] * LOG2E_OVER_T);
        }
        s0 += __shfl_xor_sync(0xffffffffu, s0, 1);
        s0 += __shfl_xor_sync(0xffffffffu, s0, 2);
        s1 += __shfl_xor_sync(0xffffffffu, s1, 1);
        s1 += __shfl_xor_sync(0xffffffffu, s1, 2);
        if (gc == 0) {
            rsum[wn][wm * 64 + mt * 16 + gr]     = s0;
            rsum[wn][wm * 64 + mt * 16 + 8 + gr] = s1;
        }
    }
    __syncthreads();
    if (t < 128)
        g_part[(size_t)(bm * BM + t) * NT_N + bn] =
            rsum[0][t] + rsum[1][t] + rsum[2][t] + rsum[3][t];
}

// -------------------- kernel 4: reduce partials -> S[row] --------------------
__global__ void reduce_S() {
    int row = blockIdx.x * 8 + (threadIdx.x >> 5);
    int l   = threadIdx.x & 31;
    float s = 0.f;
    for (int j = l; j < NT_N; j += 32) s += g_part[(size_t)row * NT_N + j];
    for (int o = 16; o > 0; o >>= 1) s += __shfl_xor_sync(0xffffffffu, s, o);
    if (l == 0) g_S[row] = s;
}

// -------------------- kernel 5: finalize loss --------------------------------
__global__ void finalize_loss(float* __restrict__ out, int out_size) {
    int t = threadIdx.x;
    float acc = 0.f;
    for (int i = t; i < B_Q; i += 512) {
        float e[4], su = 0.f, sa[4];
        #pragma unroll
        for (int n = 0; n < 4; ++n) {
            sa[n] = g_sa[i * P_POS + n];
            e[n]  = ex2f(sa[n] * LOG2E_OVER_T);
            su   += e[n];
        }
        float base = g_S[i] - ex2f(g_diag[i] * LOG2E_OVER_T) - su;
        #pragma unroll
        for (int n = 0; n < 4; ++n)
            acc += logf(base + e[n]) - sa[n] * INV_T;
    }
    __shared__ float red[512];
    red[t] = acc; __syncthreads();
    for (int s = 256; s > 0; s >>= 1) { if (t < s) red[t] += red[t + s]; __syncthreads(); }
    if (t == 0) {
        float loss = red[0] / (float)(B_Q * P_POS);
        for (int j = 0; j < out_size; ++j) out[j] = loss;
    }
}

// -------------------- launch --------------------------------------------------
extern "C" void kernel_launch(void* const* d_in, const int* in_sizes, int n_in,
                              void* d_out, int out_size) {
    (void)in_sizes; (void)n_in;
    const float* q    = (const float*)d_in[0];
    const float* docs = (const float*)d_in[1];
    float* out        = (float*)d_out;

    cudaFuncSetAttribute(gemm_exp_rowsum, cudaFuncAttributeMaxDynamicSharedMemorySize, SM_DYN);

    prep_normalize<<<N_KEY, 256>>>(q, docs);
    pos_diag_dots<<<B_Q, 160>>>();
    gemm_exp_rowsum<<<dim3(NT_N, NT_M), 256, SM_DYN>>>();
    reduce_S<<<B_Q / 8, 256>>>();
    finalize_loss<<<1, 512>>>(out, out_size);
}